// round 2
// baseline (speedup 1.0000x reference)
#include <cuda_runtime.h>

#define R 2048
#define T 4096
#define NBLK 128
#define NTHREADS 256

// Scratch (static __device__ arrays — no allocation anywhere)
__device__ float g_B[(size_t)T * R];   // 32 MB: precomputed input+feedback bias
__device__ float g_X[(size_t)T * R];   // 32 MB: reservoir states (row 0 = zeros)
__device__ int   g_done[T];            // per-step arrival counters

__device__ __forceinline__ int ld_acq(const int* p) {
    int v;
    asm volatile("ld.global.acquire.gpu.b32 %0, [%1];" : "=r"(v) : "l"(p) : "memory");
    return v;
}

__device__ __forceinline__ void red_release_add(int* p, int v) {
    asm volatile("red.release.gpu.global.add.u32 [%0], %1;" :: "l"(p), "r"(v) : "memory");
}

// packed dual-FMA: acc = a*b + acc on (f32,f32) pairs held in u64
__device__ __forceinline__ void fma2(unsigned long long& acc,
                                     unsigned long long a,
                                     unsigned long long b) {
    asm volatile("fma.rn.f32x2 %0, %1, %2, %0;" : "+l"(acc) : "l"(a), "l"(b));
}

__device__ __forceinline__ float lo_f(unsigned long long v) {
    return __uint_as_float((unsigned)(v & 0xffffffffull));
}
__device__ __forceinline__ float hi_f(unsigned long long v) {
    return __uint_as_float((unsigned)(v >> 32));
}

// fast tanh: 1 - 2/(e^{2x}+1); handles +-inf limits correctly, rel err ~1e-6
__device__ __forceinline__ float fast_tanh(float x) {
    float e = __expf(2.0f * x);
    return 1.0f - __fdividef(2.0f, e + 1.0f);
}

// ---------------------------------------------------------------------------
// Kernel 0: reset counters + zero state row 0 (runs every launch: graph-safe)
// ---------------------------------------------------------------------------
__global__ void init_kernel() {
    int tid = blockIdx.x * blockDim.x + threadIdx.x;
    int stride = gridDim.x * blockDim.x;
    for (int n = tid; n < T; n += stride) g_done[n] = (n == 0) ? NBLK : 0;
    for (int i = tid; i < R; i += stride) g_X[i] = 0.0f;
}

// ---------------------------------------------------------------------------
// Kernel 1: B[n][i] = w_in[i,:]@inputs[n] + w_feedb[i,:]@outputs[n-1], n>=1
// ---------------------------------------------------------------------------
__global__ void precomp_kernel(const float* __restrict__ inputs,
                               const float* __restrict__ outputs,
                               const float* __restrict__ w_in,
                               const float* __restrict__ w_feedb) {
    const int i = blockIdx.x * 256 + threadIdx.x;  // 0..2047 (grid.x = 8)
    float wi[8], wf[4];
#pragma unroll
    for (int k = 0; k < 8; k++) wi[k] = w_in[i * 8 + k];
#pragma unroll
    for (int k = 0; k < 4; k++) wf[k] = w_feedb[i * 4 + k];
    int n0 = blockIdx.y * 128;          // grid.y = 32
    int n1 = n0 + 128;
    if (n0 == 0) n0 = 1;
    for (int n = n0; n < n1; n++) {
        float s = 0.0f;
#pragma unroll
        for (int k = 0; k < 8; k++) s = fmaf(wi[k], inputs[n * 8 + k], s);
#pragma unroll
        for (int k = 0; k < 4; k++) s = fmaf(wf[k], outputs[(n - 1) * 4 + k], s);
        g_B[(size_t)n * R + i] = s;
    }
}

// ---------------------------------------------------------------------------
// Kernel 2: persistent recurrence. 128 blocks x 256 threads.
// Block b owns rows [16b, 16b+16). Warp w owns rows 16b+2w, 16b+2w+1.
// Each lane holds 64 W values per row as 16 ulonglong2 (packed f32 pairs).
// ---------------------------------------------------------------------------
__global__ __launch_bounds__(NTHREADS, 1)
void recur_kernel(const float* __restrict__ w, const float* __restrict__ noise) {
    const int tid  = threadIdx.x;
    const int warp = tid >> 5;
    const int lane = tid & 31;
    const int r0   = blockIdx.x * 16 + warp * 2;

    // Load W rows into registers once (persist across all 4096 steps)
    ulonglong2 w0[16], w1[16];
    const ulonglong2* wr0 = reinterpret_cast<const ulonglong2*>(w + (size_t)r0 * R);
    const ulonglong2* wr1 = reinterpret_cast<const ulonglong2*>(w + (size_t)(r0 + 1) * R);
#pragma unroll
    for (int k = 0; k < 16; ++k) {
        w0[k] = wr0[lane + 32 * k];
        w1[k] = wr1[lane + 32 * k];
    }

    for (int n = 1; n < T; ++n) {
        // Prefetch bias + noise (independent of x) before the spin
        float bn0 = 0.f, bn1 = 0.f, nz0 = 0.f, nz1 = 0.f;
        if (lane == 0) {
            bn0 = g_B[(size_t)n * R + r0];
            bn1 = g_B[(size_t)n * R + r0 + 1];
            nz0 = noise[(size_t)n * R + r0];
            nz1 = noise[(size_t)n * R + r0 + 1];
        }

        // All warps spin; each proceeds the instant the counter lands.
        {
            const int* flag = &g_done[n - 1];
            while (ld_acq(flag) < NBLK) { __nanosleep(32); }
        }

        const ulonglong2* x2 =
            reinterpret_cast<const ulonglong2*>(g_X + (size_t)(n - 1) * R);
        unsigned long long a0 = 0ull, a1 = 0ull, b0 = 0ull, b1 = 0ull;
#pragma unroll
        for (int k = 0; k < 16; ++k) {
            ulonglong2 xa = x2[lane + 32 * k];
            fma2(a0, w0[k].x, xa.x);
            fma2(a1, w0[k].y, xa.y);
            fma2(b0, w1[k].x, xa.x);
            fma2(b1, w1[k].y, xa.y);
        }
        float s0 = (lo_f(a0) + hi_f(a0)) + (lo_f(a1) + hi_f(a1));
        float s1 = (lo_f(b0) + hi_f(b0)) + (lo_f(b1) + hi_f(b1));
#pragma unroll
        for (int off = 16; off > 0; off >>= 1) {
            s0 += __shfl_xor_sync(0xffffffffu, s0, off);
            s1 += __shfl_xor_sync(0xffffffffu, s1, off);
        }
        if (lane == 0) {
            float2 v;
            v.x = fast_tanh(s0 + bn0) + nz0;
            v.y = fast_tanh(s1 + bn1) + nz1;
            *reinterpret_cast<float2*>(g_X + (size_t)n * R + r0) = v;
        }
        __syncthreads();
        if (tid == 0) {
            // release covers the block's stores (they happen-before via bar.sync)
            red_release_add(&g_done[n], 1);
        }
    }
}

// ---------------------------------------------------------------------------
// Kernel 3: readout. out[n] = lin_w[:, :R]@x_n + lin_w[:, R:]@u_n + lin_b
// One block per n, 256 threads.
// ---------------------------------------------------------------------------
__global__ void readout_kernel(const float* __restrict__ inputs,
                               const float* __restrict__ lin_w,
                               const float* __restrict__ lin_b,
                               float* __restrict__ out) {
    const int n   = blockIdx.x;
    const int tid = threadIdx.x;
    if (n == 0) {
        if (tid < 4) out[tid] = lin_b[tid];
        return;
    }
    const int FAN = R + 8;  // 2056
    float acc0 = 0.f, acc1 = 0.f, acc2 = 0.f, acc3 = 0.f;
    const float* xr = g_X + (size_t)n * R;
    for (int i = tid; i < R; i += 256) {
        float xv = xr[i];
        acc0 = fmaf(lin_w[0 * FAN + i], xv, acc0);
        acc1 = fmaf(lin_w[1 * FAN + i], xv, acc1);
        acc2 = fmaf(lin_w[2 * FAN + i], xv, acc2);
        acc3 = fmaf(lin_w[3 * FAN + i], xv, acc3);
    }
#pragma unroll
    for (int off = 16; off > 0; off >>= 1) {
        acc0 += __shfl_xor_sync(0xffffffffu, acc0, off);
        acc1 += __shfl_xor_sync(0xffffffffu, acc1, off);
        acc2 += __shfl_xor_sync(0xffffffffu, acc2, off);
        acc3 += __shfl_xor_sync(0xffffffffu, acc3, off);
    }
    __shared__ float red[8][4];
    int warp = tid >> 5, lane = tid & 31;
    if (lane == 0) {
        red[warp][0] = acc0; red[warp][1] = acc1;
        red[warp][2] = acc2; red[warp][3] = acc3;
    }
    __syncthreads();
    if (tid < 4) {
        float s = 0.f;
#pragma unroll
        for (int wp = 0; wp < 8; wp++) s += red[wp][tid];
        float inp = 0.f;
#pragma unroll
        for (int k = 0; k < 8; k++)
            inp = fmaf(lin_w[tid * FAN + R + k], inputs[n * 8 + k], inp);
        out[n * 4 + tid] = s + inp + lin_b[tid];
    }
}

// ---------------------------------------------------------------------------
// Launch: init -> precompute B -> persistent recurrence -> readout
// ---------------------------------------------------------------------------
extern "C" void kernel_launch(void* const* d_in, const int* in_sizes, int n_in,
                              void* d_out, int out_size) {
    const float* inputs  = (const float*)d_in[0];
    const float* outputs = (const float*)d_in[1];
    const float* w       = (const float*)d_in[2];
    const float* w_in    = (const float*)d_in[3];
    const float* w_feedb = (const float*)d_in[4];
    const float* lin_w   = (const float*)d_in[5];
    const float* lin_b   = (const float*)d_in[6];
    const float* noise   = (const float*)d_in[7];
    float* out = (float*)d_out;

    init_kernel<<<8, 256>>>();
    precomp_kernel<<<dim3(8, 32), 256>>>(inputs, outputs, w_in, w_feedb);
    recur_kernel<<<NBLK, NTHREADS>>>(w, noise);
    readout_kernel<<<T, 256>>>(inputs, lin_w, lin_b, out);
}

// round 3
// speedup vs baseline: 1.2988x; 1.2988x over previous
#include <cuda_runtime.h>

#define R 2048
#define T 4096
#define NBLK 128
#define NTHREADS 256

// Scratch (static __device__ arrays — no allocation anywhere)
__device__ float g_B[(size_t)T * R];   // 32 MB: precomputed input+feedback bias
__device__ float g_X[(size_t)T * R];   // 32 MB: reservoir states (row 0 = zeros)
__device__ int   g_done[T];            // per-step arrival counters

__device__ __forceinline__ int ld_acq(const int* p) {
    int v;
    asm volatile("ld.global.acquire.gpu.b32 %0, [%1];" : "=r"(v) : "l"(p) : "memory");
    return v;
}

__device__ __forceinline__ void red_release_add(int* p, int v) {
    asm volatile("red.release.gpu.global.add.u32 [%0], %1;" :: "l"(p), "r"(v) : "memory");
}

// packed dual-FMA: acc = a*b + acc on (f32,f32) pairs held in u64
__device__ __forceinline__ void fma2(unsigned long long& acc,
                                     unsigned long long a,
                                     unsigned long long b) {
    asm volatile("fma.rn.f32x2 %0, %1, %2, %0;" : "+l"(acc) : "l"(a), "l"(b));
}

__device__ __forceinline__ float lo_f(unsigned long long v) {
    return __uint_as_float((unsigned)(v & 0xffffffffull));
}
__device__ __forceinline__ float hi_f(unsigned long long v) {
    return __uint_as_float((unsigned)(v >> 32));
}

// fast tanh: 1 - 2/(e^{2x}+1); correct +-1 limits, rel err ~1e-6
__device__ __forceinline__ float fast_tanh(float x) {
    float e = __expf(2.0f * x);
    return 1.0f - __fdividef(2.0f, e + 1.0f);
}

// ---------------------------------------------------------------------------
// Kernel 0: reset counters + zero state row 0 (runs every launch: graph-safe)
// ---------------------------------------------------------------------------
__global__ void init_kernel() {
    int tid = blockIdx.x * blockDim.x + threadIdx.x;
    int stride = gridDim.x * blockDim.x;
    for (int n = tid; n < T; n += stride) g_done[n] = (n == 0) ? NBLK : 0;
    for (int i = tid; i < R; i += stride) g_X[i] = 0.0f;
}

// ---------------------------------------------------------------------------
// Kernel 1: B[n][i] = w_in[i,:]@inputs[n] + w_feedb[i,:]@outputs[n-1], n>=1
// ---------------------------------------------------------------------------
__global__ void precomp_kernel(const float* __restrict__ inputs,
                               const float* __restrict__ outputs,
                               const float* __restrict__ w_in,
                               const float* __restrict__ w_feedb) {
    const int i = blockIdx.x * 256 + threadIdx.x;  // 0..2047 (grid.x = 8)
    float wi[8], wf[4];
#pragma unroll
    for (int k = 0; k < 8; k++) wi[k] = w_in[i * 8 + k];
#pragma unroll
    for (int k = 0; k < 4; k++) wf[k] = w_feedb[i * 4 + k];
    int n0 = blockIdx.y * 128;          // grid.y = 32
    int n1 = n0 + 128;
    if (n0 == 0) n0 = 1;
    for (int n = n0; n < n1; n++) {
        float s = 0.0f;
#pragma unroll
        for (int k = 0; k < 8; k++) s = fmaf(wi[k], inputs[n * 8 + k], s);
#pragma unroll
        for (int k = 0; k < 4; k++) s = fmaf(wf[k], outputs[(n - 1) * 4 + k], s);
        g_B[(size_t)n * R + i] = s;
    }
}

// ---------------------------------------------------------------------------
// Kernel 2: persistent recurrence. 128 blocks x 256 threads.
// Block b owns rows [16b, 16b+16). Warp w owns rows 16b+2w, 16b+2w+1.
// Each lane holds 64 W values per row as 16 ulonglong2 (packed f32 pairs).
// Sync: ONE spinner per block (tid 0), broadcast via __syncthreads.
// ---------------------------------------------------------------------------
__global__ __launch_bounds__(NTHREADS, 1)
void recur_kernel(const float* __restrict__ w, const float* __restrict__ noise) {
    const int tid  = threadIdx.x;
    const int warp = tid >> 5;
    const int lane = tid & 31;
    const int r0   = blockIdx.x * 16 + warp * 2;

    // Load W rows into registers once (persist across all 4096 steps)
    ulonglong2 w0[16], w1[16];
    const ulonglong2* wr0 = reinterpret_cast<const ulonglong2*>(w + (size_t)r0 * R);
    const ulonglong2* wr1 = reinterpret_cast<const ulonglong2*>(w + (size_t)(r0 + 1) * R);
#pragma unroll
    for (int k = 0; k < 16; ++k) {
        w0[k] = wr0[lane + 32 * k];
        w1[k] = wr1[lane + 32 * k];
    }

    for (int n = 1; n < T; ++n) {
        // Prefetch bias + noise (independent of x) before the spin
        float bn0 = 0.f, bn1 = 0.f, nz0 = 0.f, nz1 = 0.f;
        if (lane == 0) {
            bn0 = g_B[(size_t)n * R + r0];
            bn1 = g_B[(size_t)n * R + r0 + 1];
            nz0 = noise[(size_t)n * R + r0];
            nz1 = noise[(size_t)n * R + r0 + 1];
        }

        // Single spinner per block; everyone else parks at the barrier.
        if (tid == 0) {
            const int* flag = &g_done[n - 1];
            while (ld_acq(flag) < NBLK) {}
        }
        __syncthreads();

        const ulonglong2* x2 =
            reinterpret_cast<const ulonglong2*>(g_X + (size_t)(n - 1) * R);
        unsigned long long a0 = 0ull, a1 = 0ull, b0 = 0ull, b1 = 0ull;
#pragma unroll
        for (int k = 0; k < 16; ++k) {
            ulonglong2 xa = x2[lane + 32 * k];
            fma2(a0, w0[k].x, xa.x);
            fma2(a1, w0[k].y, xa.y);
            fma2(b0, w1[k].x, xa.x);
            fma2(b1, w1[k].y, xa.y);
        }
        float s0 = (lo_f(a0) + hi_f(a0)) + (lo_f(a1) + hi_f(a1));
        float s1 = (lo_f(b0) + hi_f(b0)) + (lo_f(b1) + hi_f(b1));
#pragma unroll
        for (int off = 16; off > 0; off >>= 1) {
            s0 += __shfl_xor_sync(0xffffffffu, s0, off);
            s1 += __shfl_xor_sync(0xffffffffu, s1, off);
        }
        if (lane == 0) {
            float2 v;
            v.x = fast_tanh(s0 + bn0) + nz0;
            v.y = fast_tanh(s1 + bn1) + nz1;
            *reinterpret_cast<float2*>(g_X + (size_t)n * R + r0) = v;
        }
        __syncthreads();
        if (tid == 0) {
            // release covers the block's stores (they happen-before via bar.sync)
            red_release_add(&g_done[n], 1);
        }
    }
}

// ---------------------------------------------------------------------------
// Kernel 3: readout. out[n] = lin_w[:, :R]@x_n + lin_w[:, R:]@u_n + lin_b
// One block per n, 256 threads.
// ---------------------------------------------------------------------------
__global__ void readout_kernel(const float* __restrict__ inputs,
                               const float* __restrict__ lin_w,
                               const float* __restrict__ lin_b,
                               float* __restrict__ out) {
    const int n   = blockIdx.x;
    const int tid = threadIdx.x;
    if (n == 0) {
        if (tid < 4) out[tid] = lin_b[tid];
        return;
    }
    const int FAN = R + 8;  // 2056
    float acc0 = 0.f, acc1 = 0.f, acc2 = 0.f, acc3 = 0.f;
    const float* xr = g_X + (size_t)n * R;
    for (int i = tid; i < R; i += 256) {
        float xv = xr[i];
        acc0 = fmaf(lin_w[0 * FAN + i], xv, acc0);
        acc1 = fmaf(lin_w[1 * FAN + i], xv, acc1);
        acc2 = fmaf(lin_w[2 * FAN + i], xv, acc2);
        acc3 = fmaf(lin_w[3 * FAN + i], xv, acc3);
    }
#pragma unroll
    for (int off = 16; off > 0; off >>= 1) {
        acc0 += __shfl_xor_sync(0xffffffffu, acc0, off);
        acc1 += __shfl_xor_sync(0xffffffffu, acc1, off);
        acc2 += __shfl_xor_sync(0xffffffffu, acc2, off);
        acc3 += __shfl_xor_sync(0xffffffffu, acc3, off);
    }
    __shared__ float red[8][4];
    int warp = tid >> 5, lane = tid & 31;
    if (lane == 0) {
        red[warp][0] = acc0; red[warp][1] = acc1;
        red[warp][2] = acc2; red[warp][3] = acc3;
    }
    __syncthreads();
    if (tid < 4) {
        float s = 0.f;
#pragma unroll
        for (int wp = 0; wp < 8; wp++) s += red[wp][tid];
        float inp = 0.f;
#pragma unroll
        for (int k = 0; k < 8; k++)
            inp = fmaf(lin_w[tid * FAN + R + k], inputs[n * 8 + k], inp);
        out[n * 4 + tid] = s + inp + lin_b[tid];
    }
}

// ---------------------------------------------------------------------------
// Launch: init -> precompute B -> persistent recurrence -> readout
// ---------------------------------------------------------------------------
extern "C" void kernel_launch(void* const* d_in, const int* in_sizes, int n_in,
                              void* d_out, int out_size) {
    const float* inputs  = (const float*)d_in[0];
    const float* outputs = (const float*)d_in[1];
    const float* w       = (const float*)d_in[2];
    const float* w_in    = (const float*)d_in[3];
    const float* w_feedb = (const float*)d_in[4];
    const float* lin_w   = (const float*)d_in[5];
    const float* lin_b   = (const float*)d_in[6];
    const float* noise   = (const float*)d_in[7];
    float* out = (float*)d_out;

    init_kernel<<<8, 256>>>();
    precomp_kernel<<<dim3(8, 32), 256>>>(inputs, outputs, w_in, w_feedb);
    recur_kernel<<<NBLK, NTHREADS>>>(w, noise);
    readout_kernel<<<T, 256>>>(inputs, lin_w, lin_b, out);
}

// round 4
// speedup vs baseline: 1.3618x; 1.0485x over previous
#include <cuda_runtime.h>

#define R 2048
#define T 4096
#define NBLK 128
#define NTHREADS 256

// Scratch (static __device__ arrays — no allocation anywhere)
__device__ float g_B[(size_t)T * R];   // 32 MB: precomputed input+feedback bias
__device__ float g_X[(size_t)T * R];   // 32 MB: reservoir states (row 0 = zeros)
__device__ int   g_done[T];            // per-step arrival counters

__device__ __forceinline__ int ld_acq(const int* p) {
    int v;
    asm volatile("ld.global.acquire.gpu.b32 %0, [%1];" : "=r"(v) : "l"(p) : "memory");
    return v;
}

__device__ __forceinline__ void red_release_add(int* p, int v) {
    asm volatile("red.release.gpu.global.add.u32 [%0], %1;" :: "l"(p), "r"(v) : "memory");
}

// packed dual-FMA: acc = a*b + acc on (f32,f32) pairs held in u64
__device__ __forceinline__ void fma2(unsigned long long& acc,
                                     unsigned long long a,
                                     unsigned long long b) {
    asm volatile("fma.rn.f32x2 %0, %1, %2, %0;" : "+l"(acc) : "l"(a), "l"(b));
}

__device__ __forceinline__ unsigned long long addx2(unsigned long long a,
                                                    unsigned long long b) {
    unsigned long long d;
    asm volatile("add.rn.f32x2 %0, %1, %2;" : "=l"(d) : "l"(a), "l"(b));
    return d;
}

__device__ __forceinline__ float lo_f(unsigned long long v) {
    return __uint_as_float((unsigned)(v & 0xffffffffull));
}
__device__ __forceinline__ float hi_f(unsigned long long v) {
    return __uint_as_float((unsigned)(v >> 32));
}

__device__ __forceinline__ unsigned long long pack2(float a, float b) {
    unsigned long long d;
    asm("mov.b64 %0, {%1, %2};" : "=l"(d) : "f"(a), "f"(b));
    return d;
}

// fast tanh: 1 - 2/(e^{2x}+1); correct +-1 limits, rel err ~1e-6
__device__ __forceinline__ float fast_tanh(float x) {
    float e = __expf(2.0f * x);
    return 1.0f - __fdividef(2.0f, e + 1.0f);
}

// ---------------------------------------------------------------------------
// Kernel 0: reset counters + zero state row 0 (runs every launch: graph-safe)
// ---------------------------------------------------------------------------
__global__ void init_kernel() {
    int tid = blockIdx.x * blockDim.x + threadIdx.x;
    int stride = gridDim.x * blockDim.x;
    for (int n = tid; n < T; n += stride) g_done[n] = (n == 0) ? NBLK : 0;
    for (int i = tid; i < R; i += stride) g_X[i] = 0.0f;
}

// ---------------------------------------------------------------------------
// Kernel 1: B[n][i] = w_in[i,:]@inputs[n] + w_feedb[i,:]@outputs[n-1], n>=1
// ---------------------------------------------------------------------------
__global__ void precomp_kernel(const float* __restrict__ inputs,
                               const float* __restrict__ outputs,
                               const float* __restrict__ w_in,
                               const float* __restrict__ w_feedb) {
    const int i = blockIdx.x * 256 + threadIdx.x;  // 0..2047 (grid.x = 8)
    float wi[8], wf[4];
#pragma unroll
    for (int k = 0; k < 8; k++) wi[k] = w_in[i * 8 + k];
#pragma unroll
    for (int k = 0; k < 4; k++) wf[k] = w_feedb[i * 4 + k];
    int n0 = blockIdx.y * 128;          // grid.y = 32
    int n1 = n0 + 128;
    if (n0 == 0) n0 = 1;
    for (int n = n0; n < n1; n++) {
        float s = 0.0f;
#pragma unroll
        for (int k = 0; k < 8; k++) s = fmaf(wi[k], inputs[n * 8 + k], s);
#pragma unroll
        for (int k = 0; k < 4; k++) s = fmaf(wf[k], outputs[(n - 1) * 4 + k], s);
        g_B[(size_t)n * R + i] = s;
    }
}

// ---------------------------------------------------------------------------
// Kernel 2: persistent recurrence. 128 blocks x 256 threads.
// Block b owns rows [16b, 16b+16).
// Warp layout: g = warp>>1 (4 row-groups of 4 rows), c = warp&1 (2 x-chunks
// of 1024 floats). Each warp computes 4 partial row-dots over its chunk:
// lane covers 8 ulonglong2 slots (32 floats), W in registers (128 regs).
// Cross-warp combine via SMEM; warp 0 finalizes (tanh + store + publish).
// L1tex x traffic per block-step: 32 KB (vs 64 KB with full-row warps).
// ---------------------------------------------------------------------------
__global__ __launch_bounds__(NTHREADS, 1)
void recur_kernel(const float* __restrict__ w, const float* __restrict__ noise) {
    const int tid  = threadIdx.x;
    const int warp = tid >> 5;
    const int lane = tid & 31;
    const int g    = warp >> 1;      // row-group 0..3
    const int c    = warp & 1;       // x-chunk 0..1
    const int base = blockIdx.x * 16;
    const int R0   = base + g * 4;   // first of this warp's 4 rows

    // W registers: 4 rows x 8 slots (each slot = 4 floats = ulonglong2)
    ulonglong2 Wr[4][8];
#pragma unroll
    for (int r = 0; r < 4; ++r) {
        const ulonglong2* wp =
            reinterpret_cast<const ulonglong2*>(w + (size_t)(R0 + r) * R);
#pragma unroll
        for (int j = 0; j < 8; ++j)
            Wr[r][j] = wp[256 * c + lane + 32 * j];
    }

    __shared__ float4 sm_part[2][4];   // [chunk][row-group] -> 4 row partials

    for (int n = 1; n < T; ++n) {
        // Prefetch bias + noise for the finalizer lanes (independent of x)
        float bnv = 0.f, nzv = 0.f;
        if (warp == 0 && lane < 16) {
            bnv = g_B[(size_t)n * R + base + lane];
            nzv = noise[(size_t)n * R + base + lane];
        }

        // Single spinner per block; everyone else parks at the barrier.
        if (tid == 0) {
            const int* flag = &g_done[n - 1];
            while (ld_acq(flag) < NBLK) {}
        }
        __syncthreads();

        const ulonglong2* x2 =
            reinterpret_cast<const ulonglong2*>(g_X + (size_t)(n - 1) * R) + 256 * c;

        unsigned long long acc[4][2];
#pragma unroll
        for (int r = 0; r < 4; ++r) { acc[r][0] = 0ull; acc[r][1] = 0ull; }

#pragma unroll
        for (int j = 0; j < 8; ++j) {
            ulonglong2 xv = x2[lane + 32 * j];
#pragma unroll
            for (int r = 0; r < 4; ++r) {
                fma2(acc[r][0], Wr[r][j].x, xv.x);
                fma2(acc[r][1], Wr[r][j].y, xv.y);
            }
        }

        // per-row lane-local sum, packed as (row0,row1) and (row2,row3)
        float s[4];
#pragma unroll
        for (int r = 0; r < 4; ++r) {
            unsigned long long t = addx2(acc[r][0], acc[r][1]);
            s[r] = lo_f(t) + hi_f(t);
        }
        unsigned long long p01 = pack2(s[0], s[1]);
        unsigned long long p23 = pack2(s[2], s[3]);
#pragma unroll
        for (int off = 16; off > 0; off >>= 1) {
            p01 = addx2(p01, __shfl_xor_sync(0xffffffffu, p01, off));
            p23 = addx2(p23, __shfl_xor_sync(0xffffffffu, p23, off));
        }
        if (lane == 0)
            sm_part[c][g] = make_float4(lo_f(p01), hi_f(p01), lo_f(p23), hi_f(p23));
        __syncthreads();

        // Warp 0 finalizes all 16 rows: combine chunks, tanh, store, publish
        if (warp == 0) {
            if (lane < 16) {
                const float* f0 = reinterpret_cast<const float*>(&sm_part[0][0]);
                const float* f1 = reinterpret_cast<const float*>(&sm_part[1][0]);
                float v = fast_tanh(f0[lane] + f1[lane] + bnv) + nzv;
                g_X[(size_t)n * R + base + lane] = v;
            }
            __syncwarp();
            if (lane == 0)
                red_release_add(&g_done[n], 1);  // stores ordered via syncwarp
        }
    }
}

// ---------------------------------------------------------------------------
// Kernel 3: readout. out[n] = lin_w[:, :R]@x_n + lin_w[:, R:]@u_n + lin_b
// One block per n, 256 threads.
// ---------------------------------------------------------------------------
__global__ void readout_kernel(const float* __restrict__ inputs,
                               const float* __restrict__ lin_w,
                               const float* __restrict__ lin_b,
                               float* __restrict__ out) {
    const int n   = blockIdx.x;
    const int tid = threadIdx.x;
    if (n == 0) {
        if (tid < 4) out[tid] = lin_b[tid];
        return;
    }
    const int FAN = R + 8;  // 2056
    float acc0 = 0.f, acc1 = 0.f, acc2 = 0.f, acc3 = 0.f;
    const float* xr = g_X + (size_t)n * R;
    for (int i = tid; i < R; i += 256) {
        float xv = xr[i];
        acc0 = fmaf(lin_w[0 * FAN + i], xv, acc0);
        acc1 = fmaf(lin_w[1 * FAN + i], xv, acc1);
        acc2 = fmaf(lin_w[2 * FAN + i], xv, acc2);
        acc3 = fmaf(lin_w[3 * FAN + i], xv, acc3);
    }
#pragma unroll
    for (int off = 16; off > 0; off >>= 1) {
        acc0 += __shfl_xor_sync(0xffffffffu, acc0, off);
        acc1 += __shfl_xor_sync(0xffffffffu, acc1, off);
        acc2 += __shfl_xor_sync(0xffffffffu, acc2, off);
        acc3 += __shfl_xor_sync(0xffffffffu, acc3, off);
    }
    __shared__ float red[8][4];
    int warp = tid >> 5, lane = tid & 31;
    if (lane == 0) {
        red[warp][0] = acc0; red[warp][1] = acc1;
        red[warp][2] = acc2; red[warp][3] = acc3;
    }
    __syncthreads();
    if (tid < 4) {
        float s = 0.f;
#pragma unroll
        for (int wp = 0; wp < 8; wp++) s += red[wp][tid];
        float inp = 0.f;
#pragma unroll
        for (int k = 0; k < 8; k++)
            inp = fmaf(lin_w[tid * FAN + R + k], inputs[n * 8 + k], inp);
        out[n * 4 + tid] = s + inp + lin_b[tid];
    }
}

// ---------------------------------------------------------------------------
// Launch: init -> precompute B -> persistent recurrence -> readout
// ---------------------------------------------------------------------------
extern "C" void kernel_launch(void* const* d_in, const int* in_sizes, int n_in,
                              void* d_out, int out_size) {
    const float* inputs  = (const float*)d_in[0];
    const float* outputs = (const float*)d_in[1];
    const float* w       = (const float*)d_in[2];
    const float* w_in    = (const float*)d_in[3];
    const float* w_feedb = (const float*)d_in[4];
    const float* lin_w   = (const float*)d_in[5];
    const float* lin_b   = (const float*)d_in[6];
    const float* noise   = (const float*)d_in[7];
    float* out = (float*)d_out;

    init_kernel<<<8, 256>>>();
    precomp_kernel<<<dim3(8, 32), 256>>>(inputs, outputs, w_in, w_feedb);
    recur_kernel<<<NBLK, NTHREADS>>>(w, noise);
    readout_kernel<<<T, 256>>>(inputs, lin_w, lin_b, out);
}